// round 1
// baseline (speedup 1.0000x reference)
#include <cuda_runtime.h>

#define BB 512
#define TT 256
#define CC 128
#define HH 128
#define BTH ((size_t)BB * TT * HH)

// scratch for q projection (allocation-free rule: __device__ global array)
static __device__ float g_q[BTH];

// ---------------------------------------------------------------------------
// Kernel 1: fused QKV projection.
// Grid: (B*T/64) CTAs x 256 threads. Each CTA: 64 rows x 128 cols x 3 mats.
// smem: x tile [64][129] (stride 129 => bank-conflict-free with row step 16),
//       W tile [128][128] (one matrix at a time).
// Thread microkernel: 4 rows (r0 + 16i) x 8 cols (c0..c0+7), 32 accumulators.
// ---------------------------------------------------------------------------
#define XS_STRIDE 129
#define PROJ_SMEM ((64 * XS_STRIDE + 128 * 128) * 4)

__global__ void __launch_bounds__(256) proj_kernel(
    const float* __restrict__ x,
    const float* __restrict__ Wk,
    const float* __restrict__ Wq,
    const float* __restrict__ Wv,
    float* __restrict__ out)
{
    extern __shared__ float sm[];
    float* xs = sm;                    // 64 x 129
    float* ws = sm + 64 * XS_STRIDE;   // 128 x 128

    const int t = threadIdx.x;
    const size_t row0 = (size_t)blockIdx.x * 64;

    // load x tile (coalesced float4, scalar STS due to stride 129)
    const float4* xblk = (const float4*)(x + row0 * CC);
    for (int i = t; i < 64 * 32; i += 256) {
        int r = i >> 5, c4 = i & 31;
        float4 v = xblk[i];
        float* d = &xs[r * XS_STRIDE + c4 * 4];
        d[0] = v.x; d[1] = v.y; d[2] = v.z; d[3] = v.w;
    }

    const float* Wlist[3] = {Wk, Wq, Wv};
    float* dlist[3] = {out + BTH + row0 * HH,     // k
                       g_q + row0 * HH,           // q (scratch)
                       out + 2 * BTH + row0 * HH}; // v

    const int r0 = t >> 4;         // 0..15, rows {r0 + 16i}
    const int c0 = (t & 15) * 8;   // 0..120, cols c0..c0+7

    for (int m = 0; m < 3; m++) {
        __syncthreads();
        const float4* Wg = (const float4*)Wlist[m];
        for (int i = t; i < 128 * 32; i += 256)
            ((float4*)ws)[i] = Wg[i];
        __syncthreads();

        float acc[4][8];
#pragma unroll
        for (int i = 0; i < 4; i++)
#pragma unroll
            for (int j = 0; j < 8; j++) acc[i][j] = 0.f;

#pragma unroll 4
        for (int kk = 0; kk < 128; kk++) {
            float xv[4];
#pragma unroll
            for (int i = 0; i < 4; i++)
                xv[i] = xs[(r0 + 16 * i) * XS_STRIDE + kk];
            float4 w0 = *(const float4*)&ws[kk * 128 + c0];
            float4 w1 = *(const float4*)&ws[kk * 128 + c0 + 4];
            float wv[8] = {w0.x, w0.y, w0.z, w0.w, w1.x, w1.y, w1.z, w1.w};
#pragma unroll
            for (int i = 0; i < 4; i++)
#pragma unroll
                for (int j = 0; j < 8; j++)
                    acc[i][j] = fmaf(xv[i], wv[j], acc[i][j]);
        }

        float* dst = dlist[m];
#pragma unroll
        for (int i = 0; i < 4; i++) {
            size_t r = (size_t)(r0 + 16 * i);
            float4 o0 = {acc[i][0], acc[i][1], acc[i][2], acc[i][3]};
            float4 o1 = {acc[i][4], acc[i][5], acc[i][6], acc[i][7]};
            *(float4*)&dst[r * HH + c0] = o0;
            *(float4*)&dst[r * HH + c0 + 4] = o1;
        }
    }
}

// ---------------------------------------------------------------------------
// Kernel 2: causal attention, flash-style online softmax.
// Grid: (4 q-blocks, 512 batches) x 256 threads.
// CTA handles 64 query rows; streams key tiles kt = 0..qb (causal skip).
// smem: q[64][129], k[64][129], v[64][128], S[64][65], m/l/f[64].
// ---------------------------------------------------------------------------
#define QS 129
#define VS 128
#define SS 65
#define ATTN_SMEM ((64 * QS + 64 * QS + 64 * VS + 64 * SS + 3 * 64) * 4)

__global__ void __launch_bounds__(256) attn_kernel(float* __restrict__ dout)
{
    extern __shared__ float sm[];
    float* qs  = sm;
    float* ks  = qs + 64 * QS;
    float* vs  = ks + 64 * QS;
    float* S   = vs + 64 * VS;
    float* m_s = S + 64 * SS;
    float* l_s = m_s + 64;
    float* f_s = l_s + 64;

    const int t  = threadIdx.x;
    const int qb = blockIdx.x;   // 0..3
    const int b  = blockIdx.y;   // 0..511
    const int qr0 = qb * 64;

    const float* qg = g_q + ((size_t)b * TT + qr0) * HH;
    const float* kg = dout + BTH + (size_t)b * TT * HH;
    const float* vg = dout + 2 * BTH + (size_t)b * TT * HH;

    // load q tile (stride 129)
    for (int i = t; i < 64 * 32; i += 256) {
        int r = i >> 5, c4 = i & 31;
        float4 v = ((const float4*)qg)[i];
        float* d = &qs[r * QS + c4 * 4];
        d[0] = v.x; d[1] = v.y; d[2] = v.z; d[3] = v.w;
    }
    if (t < 64) { m_s[t] = -1e30f; l_s[t] = 0.f; }

    // O accumulators: rows {rC + 16i}, cols h0..h0+7
    const int rC = t >> 4;
    const int h0 = (t & 15) * 8;
    float O[4][8];
#pragma unroll
    for (int i = 0; i < 4; i++)
#pragma unroll
        for (int j = 0; j < 8; j++) O[i][j] = 0.f;

    const float scale = 0.08838834764831845f; // 128^-0.5 (n_embd scaling)

    for (int kt = 0; kt <= qb; kt++) {
        __syncthreads();  // previous tile's smem reads done

        // load K tile (stride 129, scalar STS) and V tile (stride 128, float4)
        const float4* kgt = (const float4*)(kg + (size_t)kt * 64 * HH);
        for (int i = t; i < 64 * 32; i += 256) {
            int r = i >> 5, c4 = i & 31;
            float4 v = kgt[i];
            float* d = &ks[r * QS + c4 * 4];
            d[0] = v.x; d[1] = v.y; d[2] = v.z; d[3] = v.w;
        }
        const float4* vgt = (const float4*)(vg + (size_t)kt * 64 * HH);
        for (int i = t; i < 64 * 32; i += 256)
            ((float4*)vs)[i] = vgt[i];
        __syncthreads();

        // ---- Phase A: S = scale * q @ k^T (+ causal mask on diagonal tile)
        {
            const int rA = t >> 4;   // rows {rA + 16i}
            const int cA = t & 15;   // keys {cA + 16j} -> conflict-free LDS
            float acc[4][4];
#pragma unroll
            for (int i = 0; i < 4; i++)
#pragma unroll
                for (int j = 0; j < 4; j++) acc[i][j] = 0.f;

#pragma unroll 4
            for (int h = 0; h < 128; h++) {
                float qv[4], kv[4];
#pragma unroll
                for (int i = 0; i < 4; i++)
                    qv[i] = qs[(rA + 16 * i) * QS + h];
#pragma unroll
                for (int j = 0; j < 4; j++)
                    kv[j] = ks[(cA + 16 * j) * QS + h];
#pragma unroll
                for (int i = 0; i < 4; i++)
#pragma unroll
                    for (int j = 0; j < 4; j++)
                        acc[i][j] = fmaf(qv[i], kv[j], acc[i][j]);
            }
#pragma unroll
            for (int i = 0; i < 4; i++) {
                int r = rA + 16 * i;
#pragma unroll
                for (int j = 0; j < 4; j++) {
                    int c = cA + 16 * j;
                    float sv = acc[i][j] * scale;
                    if (kt == qb && c > r) sv = -1e30f;  // causal mask
                    S[r * SS + c] = sv;
                }
            }
        }
        __syncthreads();

        // ---- Phase B: online softmax update (4 threads per row)
        {
            const int rB = t >> 2;
            const int cb = (t & 3) * 16;
            float tm = -1e30f;
#pragma unroll
            for (int i = 0; i < 16; i++)
                tm = fmaxf(tm, S[rB * SS + cb + i]);
            tm = fmaxf(tm, __shfl_xor_sync(0xFFFFFFFFu, tm, 1));
            tm = fmaxf(tm, __shfl_xor_sync(0xFFFFFFFFu, tm, 2));

            float mo = m_s[rB];
            float nm = fmaxf(mo, tm);
            float ps = 0.f;
#pragma unroll
            for (int i = 0; i < 16; i++) {
                float p = __expf(S[rB * SS + cb + i] - nm);
                S[rB * SS + cb + i] = p;
                ps += p;
            }
            ps += __shfl_xor_sync(0xFFFFFFFFu, ps, 1);
            ps += __shfl_xor_sync(0xFFFFFFFFu, ps, 2);

            if ((t & 3) == 0) {
                float f = __expf(mo - nm);   // 0 on first tile (mo = -1e30)
                l_s[rB] = l_s[rB] * f + ps;
                m_s[rB] = nm;
                f_s[rB] = f;
            }
        }
        __syncthreads();

        // ---- Phase C: O = O*f + P @ V
        {
#pragma unroll
            for (int i = 0; i < 4; i++) {
                float fr = f_s[rC + 16 * i];
#pragma unroll
                for (int j = 0; j < 8; j++) O[i][j] *= fr;
            }
#pragma unroll 2
            for (int kk = 0; kk < 64; kk++) {
                float pv[4];
#pragma unroll
                for (int i = 0; i < 4; i++)
                    pv[i] = S[(rC + 16 * i) * SS + kk];
                float4 v0 = *(const float4*)&vs[kk * VS + h0];
                float4 v1 = *(const float4*)&vs[kk * VS + h0 + 4];
#pragma unroll
                for (int i = 0; i < 4; i++) {
                    O[i][0] = fmaf(pv[i], v0.x, O[i][0]);
                    O[i][1] = fmaf(pv[i], v0.y, O[i][1]);
                    O[i][2] = fmaf(pv[i], v0.z, O[i][2]);
                    O[i][3] = fmaf(pv[i], v0.w, O[i][3]);
                    O[i][4] = fmaf(pv[i], v1.x, O[i][4]);
                    O[i][5] = fmaf(pv[i], v1.y, O[i][5]);
                    O[i][6] = fmaf(pv[i], v1.z, O[i][6]);
                    O[i][7] = fmaf(pv[i], v1.w, O[i][7]);
                }
            }
        }
    }

    // ---- normalize and store out
#pragma unroll
    for (int i = 0; i < 4; i++) {
        int r = rC + 16 * i;
        float inv = 1.f / l_s[r];
        float4 o0 = {O[i][0] * inv, O[i][1] * inv, O[i][2] * inv, O[i][3] * inv};
        float4 o1 = {O[i][4] * inv, O[i][5] * inv, O[i][6] * inv, O[i][7] * inv};
        float* dst = dout + ((size_t)b * TT + qr0 + r) * HH + h0;
        *(float4*)dst = o0;
        *(float4*)(dst + 4) = o1;
    }
}

// ---------------------------------------------------------------------------
extern "C" void kernel_launch(void* const* d_in, const int* in_sizes, int n_in,
                              void* d_out, int out_size)
{
    const float* x  = (const float*)d_in[0];
    const float* Wk = (const float*)d_in[1];
    const float* Wq = (const float*)d_in[2];
    const float* Wv = (const float*)d_in[3];
    float* out = (float*)d_out;

    cudaFuncSetAttribute(proj_kernel, cudaFuncAttributeMaxDynamicSharedMemorySize, PROJ_SMEM);
    cudaFuncSetAttribute(attn_kernel, cudaFuncAttributeMaxDynamicSharedMemorySize, ATTN_SMEM);

    proj_kernel<<<(BB * TT) / 64, 256, PROJ_SMEM>>>(x, Wk, Wq, Wv, out);
    attn_kernel<<<dim3(4, BB), 256, ATTN_SMEM>>>(out);
}

// round 6
// speedup vs baseline: 1.7022x; 1.7022x over previous
#include <cuda_runtime.h>
#include <cstdint>

#define BB 512
#define TT 256
#define CC 128
#define HH 128
#define BTH ((size_t)BB * TT * HH)

// scratch for q projection (allocation-free rule: __device__ global array)
static __device__ float g_q[BTH];

// ============================ helpers ======================================
__device__ __forceinline__ uint32_t f2tf32(float f) {
    uint32_t r;
    asm("cvt.rna.tf32.f32 %0, %1;" : "=r"(r) : "f"(f));
    return r;
}

// m16n8k8 tf32 mma, fp32 accumulate (portable mma.sync — works on compute_103)
__device__ __forceinline__ void mma_tf32(float* c, const uint32_t* a, const uint32_t* b) {
    asm volatile(
        "mma.sync.aligned.m16n8k8.row.col.f32.tf32.tf32.f32 "
        "{%0,%1,%2,%3}, {%4,%5,%6,%7}, {%8,%9}, {%0,%1,%2,%3};"
        : "+f"(c[0]), "+f"(c[1]), "+f"(c[2]), "+f"(c[3])
        : "r"(a[0]), "r"(a[1]), "r"(a[2]), "r"(a[3]), "r"(b[0]), "r"(b[1]));
}

// ---------------------------------------------------------------------------
// Kernel 1: fused QKV projection via mma.sync tf32.
// Grid: B*T/128 = 1024 CTAs x 256 threads (8 warps).
// Per CTA: out[128x128] = x[128x128] @ W[128x128], for Wk, Wq, Wv.
// Warp w: rows mb=(w&3)*32, cols nb=(w>>2)*64. 2 m-tiles x 8 n-tiles of m16n8.
// smem stride 136 words: 136%32==8 -> A-frag bank = 8*g+tq, B-frag = 8*tq+g,
// both conflict-free.
// ---------------------------------------------------------------------------
#define PSTR 136
#define PROJ_SMEM (2 * 128 * PSTR * 4)

__global__ void __launch_bounds__(256) proj_kernel(
    const float* __restrict__ x,
    const float* __restrict__ Wk,
    const float* __restrict__ Wq,
    const float* __restrict__ Wv,
    float* __restrict__ out)
{
    extern __shared__ uint32_t usm[];
    uint32_t* xs = usm;               // 128 x 136 (tf32 bits)
    uint32_t* ws = usm + 128 * PSTR;  // 128 x 136 (tf32 bits / fp32 staging)

    const int t    = threadIdx.x;
    const int warp = t >> 5;
    const int lane = t & 31;
    const int g  = lane >> 2;   // 0..7
    const int tq = lane & 3;    // 0..3
    const size_t row0 = (size_t)blockIdx.x * 128;

    // load x tile [128 x 128] -> xs (tf32)
    {
        const float4* xg = (const float4*)(x + row0 * CC);
        for (int i = t; i < 128 * 32; i += 256) {
            int r = i >> 5, c = (i & 31) * 4;
            float4 v = xg[i];
            uint32_t* d = &xs[r * PSTR + c];
            d[0] = f2tf32(v.x); d[1] = f2tf32(v.y);
            d[2] = f2tf32(v.z); d[3] = f2tf32(v.w);
        }
    }

    const float* Wlist[3] = {Wk, Wq, Wv};
    float* dlist[3] = {out + BTH + row0 * HH,       // k
                       g_q + row0 * HH,             // q
                       out + 2 * BTH + row0 * HH};  // v

    const int mb = (warp & 3) * 32;
    const int nb = (warp >> 2) * 64;

    for (int m = 0; m < 3; m++) {
        __syncthreads();   // prior epilogue readers of ws are done
        // load W [k=128][n=128] -> ws (tf32)
        {
            const float4* Wg = (const float4*)Wlist[m];
            for (int i = t; i < 128 * 32; i += 256) {
                int kr = i >> 5, n = (i & 31) * 4;
                float4 v = Wg[i];
                uint32_t* d = &ws[kr * PSTR + n];
                d[0] = f2tf32(v.x); d[1] = f2tf32(v.y);
                d[2] = f2tf32(v.z); d[3] = f2tf32(v.w);
            }
        }
        __syncthreads();

        float acc[2][8][4];
#pragma unroll
        for (int mi = 0; mi < 2; mi++)
#pragma unroll
            for (int ni = 0; ni < 8; ni++)
#pragma unroll
                for (int j = 0; j < 4; j++) acc[mi][ni][j] = 0.f;

#pragma unroll 4
        for (int k0 = 0; k0 < 16; k0++) {
            const int k = k0 * 8;
            uint32_t a[2][4], b[8][2];
#pragma unroll
            for (int mi = 0; mi < 2; mi++) {
                int r = mb + mi * 16 + g;
                a[mi][0] = xs[r * PSTR + k + tq];
                a[mi][1] = xs[(r + 8) * PSTR + k + tq];
                a[mi][2] = xs[r * PSTR + k + tq + 4];
                a[mi][3] = xs[(r + 8) * PSTR + k + tq + 4];
            }
#pragma unroll
            for (int ni = 0; ni < 8; ni++) {
                int col = nb + ni * 8 + g;
                b[ni][0] = ws[(k + tq) * PSTR + col];
                b[ni][1] = ws[(k + tq + 4) * PSTR + col];
            }
#pragma unroll
            for (int mi = 0; mi < 2; mi++)
#pragma unroll
                for (int ni = 0; ni < 8; ni++)
                    mma_tf32(acc[mi][ni], a[mi], b[ni]);
        }

        __syncthreads();   // all mma reads of ws done -> reuse as staging
        float* stg = (float*)ws;
#pragma unroll
        for (int mi = 0; mi < 2; mi++) {
#pragma unroll
            for (int ni = 0; ni < 8; ni++) {
                int r = mb + mi * 16 + g;
                int c = nb + ni * 8 + 2 * tq;
                float2 lo = {acc[mi][ni][0], acc[mi][ni][1]};
                float2 hi = {acc[mi][ni][2], acc[mi][ni][3]};
                *(float2*)&stg[r * PSTR + c] = lo;
                *(float2*)&stg[(r + 8) * PSTR + c] = hi;
            }
        }
        __syncthreads();

        float* dst = dlist[m];
        for (int i = t; i < 128 * 32; i += 256) {
            int r = i >> 5, c = (i & 31) * 4;
            *(float4*)&dst[(size_t)r * HH + c] = *(float4*)&stg[r * PSTR + c];
        }
    }
}

// ---------------------------------------------------------------------------
// Kernel 2: causal flash attention (fp32 SIMT, LDS.128-vectorized).
// Grid: (4 q-blocks, 512 batches) x 256 threads.
// ---------------------------------------------------------------------------
#define QS 132
#define VS 128
#define SS 68
#define ATTN_SMEM ((64 * QS + 64 * QS + 64 * VS + 64 * SS + 3 * 64) * 4)

__global__ void __launch_bounds__(256) attn_kernel(float* __restrict__ dout)
{
    extern __shared__ float sm[];
    float* qs  = sm;
    float* ks  = qs + 64 * QS;
    float* vs  = ks + 64 * QS;
    float* S   = vs + 64 * VS;
    float* m_s = S + 64 * SS;
    float* l_s = m_s + 64;
    float* f_s = l_s + 64;

    const int t  = threadIdx.x;
    const int qb = blockIdx.x;
    const int b  = blockIdx.y;
    const int qr0 = qb * 64;

    const float* qg = g_q + ((size_t)b * TT + qr0) * HH;
    const float* kg = dout + BTH + (size_t)b * TT * HH;
    const float* vg = dout + 2 * BTH + (size_t)b * TT * HH;

    for (int i = t; i < 64 * 32; i += 256) {
        int r = i >> 5, c4 = i & 31;
        *(float4*)&qs[r * QS + c4 * 4] = ((const float4*)qg)[i];
    }
    if (t < 64) { m_s[t] = -1e30f; l_s[t] = 0.f; }

    const int rC = t >> 4;
    const int h0 = (t & 15) * 8;
    float O[4][8];
#pragma unroll
    for (int i = 0; i < 4; i++)
#pragma unroll
        for (int j = 0; j < 8; j++) O[i][j] = 0.f;

    const float scale = 0.08838834764831845f;  // 128^-0.5 (n_embd scaling)

    for (int kt = 0; kt <= qb; kt++) {
        __syncthreads();
        const float4* kgt = (const float4*)(kg + (size_t)kt * 64 * HH);
        const float4* vgt = (const float4*)(vg + (size_t)kt * 64 * HH);
        for (int i = t; i < 64 * 32; i += 256) {
            int r = i >> 5, c4 = i & 31;
            *(float4*)&ks[r * QS + c4 * 4] = kgt[i];
            ((float4*)vs)[i] = vgt[i];
        }
        __syncthreads();

        // ---- Phase A: S = scale * q @ k^T (LDS.128)
        {
            const int rA = t >> 4;
            const int cA = t & 15;
            float acc[4][4];
#pragma unroll
            for (int i = 0; i < 4; i++)
#pragma unroll
                for (int j = 0; j < 4; j++) acc[i][j] = 0.f;

#pragma unroll 8
            for (int h4 = 0; h4 < 32; h4++) {
                float4 qv[4], kv[4];
#pragma unroll
                for (int i = 0; i < 4; i++)
                    qv[i] = *(const float4*)&qs[(rA + 16 * i) * QS + h4 * 4];
#pragma unroll
                for (int j = 0; j < 4; j++)
                    kv[j] = *(const float4*)&ks[(cA + 16 * j) * QS + h4 * 4];
#pragma unroll
                for (int i = 0; i < 4; i++)
#pragma unroll
                    for (int j = 0; j < 4; j++) {
                        acc[i][j] = fmaf(qv[i].x, kv[j].x, acc[i][j]);
                        acc[i][j] = fmaf(qv[i].y, kv[j].y, acc[i][j]);
                        acc[i][j] = fmaf(qv[i].z, kv[j].z, acc[i][j]);
                        acc[i][j] = fmaf(qv[i].w, kv[j].w, acc[i][j]);
                    }
            }
#pragma unroll
            for (int i = 0; i < 4; i++) {
                int r = rA + 16 * i;
#pragma unroll
                for (int j = 0; j < 4; j++) {
                    int c = cA + 16 * j;
                    float sv = acc[i][j] * scale;
                    if (kt == qb && c > r) sv = -1e30f;
                    S[r * SS + c] = sv;
                }
            }
        }
        __syncthreads();

        // ---- Phase B: online softmax (4 threads/row)
        {
            const int rB = t >> 2;
            const int cbB = (t & 3) * 16;
            float tm = -1e30f;
#pragma unroll
            for (int i = 0; i < 16; i++)
                tm = fmaxf(tm, S[rB * SS + cbB + i]);
            tm = fmaxf(tm, __shfl_xor_sync(0xFFFFFFFFu, tm, 1));
            tm = fmaxf(tm, __shfl_xor_sync(0xFFFFFFFFu, tm, 2));

            float mo = m_s[rB];
            float nm = fmaxf(mo, tm);
            float ps = 0.f;
#pragma unroll
            for (int i = 0; i < 16; i++) {
                float p = __expf(S[rB * SS + cbB + i] - nm);
                S[rB * SS + cbB + i] = p;
                ps += p;
            }
            ps += __shfl_xor_sync(0xFFFFFFFFu, ps, 1);
            ps += __shfl_xor_sync(0xFFFFFFFFu, ps, 2);

            if ((t & 3) == 0) {
                float f = __expf(mo - nm);
                l_s[rB] = l_s[rB] * f + ps;
                m_s[rB] = nm;
                f_s[rB] = f;
            }
        }
        __syncthreads();

        // ---- Phase C: O = O*f + P @ V (LDS.128)
        {
#pragma unroll
            for (int i = 0; i < 4; i++) {
                float fr = f_s[rC + 16 * i];
#pragma unroll
                for (int j = 0; j < 8; j++) O[i][j] *= fr;
            }
#pragma unroll 4
            for (int k4 = 0; k4 < 16; k4++) {
                float4 pv[4];
#pragma unroll
                for (int i = 0; i < 4; i++)
                    pv[i] = *(const float4*)&S[(rC + 16 * i) * SS + k4 * 4];
#pragma unroll
                for (int u = 0; u < 4; u++) {
                    int kk = k4 * 4 + u;
                    float4 v0 = *(const float4*)&vs[kk * VS + h0];
                    float4 v1 = *(const float4*)&vs[kk * VS + h0 + 4];
#pragma unroll
                    for (int i = 0; i < 4; i++) {
                        float p = (u == 0) ? pv[i].x : (u == 1) ? pv[i].y
                                : (u == 2) ? pv[i].z : pv[i].w;
                        O[i][0] = fmaf(p, v0.x, O[i][0]);
                        O[i][1] = fmaf(p, v0.y, O[i][1]);
                        O[i][2] = fmaf(p, v0.z, O[i][2]);
                        O[i][3] = fmaf(p, v0.w, O[i][3]);
                        O[i][4] = fmaf(p, v1.x, O[i][4]);
                        O[i][5] = fmaf(p, v1.y, O[i][5]);
                        O[i][6] = fmaf(p, v1.z, O[i][6]);
                        O[i][7] = fmaf(p, v1.w, O[i][7]);
                    }
                }
            }
        }
    }

    // normalize + store
#pragma unroll
    for (int i = 0; i < 4; i++) {
        int r = rC + 16 * i;
        float inv = 1.f / l_s[r];
        float4 o0 = {O[i][0] * inv, O[i][1] * inv, O[i][2] * inv, O[i][3] * inv};
        float4 o1 = {O[i][4] * inv, O[i][5] * inv, O[i][6] * inv, O[i][7] * inv};
        float* dst = dout + ((size_t)b * TT + qr0 + r) * HH + h0;
        *(float4*)dst = o0;
        *(float4*)(dst + 4) = o1;
    }
}

// ---------------------------------------------------------------------------
extern "C" void kernel_launch(void* const* d_in, const int* in_sizes, int n_in,
                              void* d_out, int out_size)
{
    const float* x  = (const float*)d_in[0];
    const float* Wk = (const float*)d_in[1];
    const float* Wq = (const float*)d_in[2];
    const float* Wv = (const float*)d_in[3];
    float* out = (float*)d_out;

    cudaFuncSetAttribute(proj_kernel, cudaFuncAttributeMaxDynamicSharedMemorySize, PROJ_SMEM);
    cudaFuncSetAttribute(attn_kernel, cudaFuncAttributeMaxDynamicSharedMemorySize, ATTN_SMEM);

    proj_kernel<<<(BB * TT) / 128, 256, PROJ_SMEM>>>(x, Wk, Wq, Wv, out);
    attn_kernel<<<dim3(4, BB), 256, ATTN_SMEM>>>(out);
}

// round 9
// speedup vs baseline: 2.2167x; 1.3023x over previous
#include <cuda_runtime.h>
#include <cstdint>

#define BB 512
#define TT 256
#define CC 128
#define HH 128
#define BTH ((size_t)BB * TT * HH)

// scratch for q projection: holds tf32 BITS of q*scale (written by proj)
static __device__ float g_q[BTH];

// ============================ helpers ======================================
__device__ __forceinline__ uint32_t f2tf32(float f) {
    uint32_t r;
    asm("cvt.rna.tf32.f32 %0, %1;" : "=r"(r) : "f"(f));
    return r;
}

// m16n8k8 tf32 mma, fp32 accumulate (portable mma.sync — works on compute_103)
__device__ __forceinline__ void mma_tf32(float* c, const uint32_t* a, const uint32_t* b) {
    asm volatile(
        "mma.sync.aligned.m16n8k8.row.col.f32.tf32.tf32.f32 "
        "{%0,%1,%2,%3}, {%4,%5,%6,%7}, {%8,%9}, {%0,%1,%2,%3};"
        : "+f"(c[0]), "+f"(c[1]), "+f"(c[2]), "+f"(c[3])
        : "r"(a[0]), "r"(a[1]), "r"(a[2]), "r"(a[3]), "r"(b[0]), "r"(b[1]));
}

#define SCALE 0.08838834764831845f  // 128^-0.5 (n_embd scaling)

// ---------------------------------------------------------------------------
// Kernel 1: fused QKV projection via mma.sync tf32 (validated R6).
// q output: tf32 bits of q*SCALE into g_q (consumed by attn mma directly).
// ---------------------------------------------------------------------------
#define PSTR 136
#define PROJ_SMEM (2 * 128 * PSTR * 4)

__global__ void __launch_bounds__(256) proj_kernel(
    const float* __restrict__ x,
    const float* __restrict__ Wk,
    const float* __restrict__ Wq,
    const float* __restrict__ Wv,
    float* __restrict__ out)
{
    extern __shared__ uint32_t usm[];
    uint32_t* xs = usm;               // 128 x 136 (tf32 bits)
    uint32_t* ws = usm + 128 * PSTR;  // 128 x 136 (tf32 bits / fp32 staging)

    const int t    = threadIdx.x;
    const int warp = t >> 5;
    const int lane = t & 31;
    const int g  = lane >> 2;
    const int tq = lane & 3;
    const size_t row0 = (size_t)blockIdx.x * 128;

    {
        const float4* xg = (const float4*)(x + row0 * CC);
        for (int i = t; i < 128 * 32; i += 256) {
            int r = i >> 5, c = (i & 31) * 4;
            float4 v = xg[i];
            uint32_t* d = &xs[r * PSTR + c];
            d[0] = f2tf32(v.x); d[1] = f2tf32(v.y);
            d[2] = f2tf32(v.z); d[3] = f2tf32(v.w);
        }
    }

    const float* Wlist[3] = {Wk, Wq, Wv};
    float* dlist[3] = {out + BTH + row0 * HH,       // k
                       g_q + row0 * HH,             // q (tf32 bits, scaled)
                       out + 2 * BTH + row0 * HH};  // v

    const int mb = (warp & 3) * 32;
    const int nb = (warp >> 2) * 64;

    for (int m = 0; m < 3; m++) {
        __syncthreads();
        {
            const float4* Wg = (const float4*)Wlist[m];
            for (int i = t; i < 128 * 32; i += 256) {
                int kr = i >> 5, n = (i & 31) * 4;
                float4 v = Wg[i];
                uint32_t* d = &ws[kr * PSTR + n];
                d[0] = f2tf32(v.x); d[1] = f2tf32(v.y);
                d[2] = f2tf32(v.z); d[3] = f2tf32(v.w);
            }
        }
        __syncthreads();

        float acc[2][8][4];
#pragma unroll
        for (int mi = 0; mi < 2; mi++)
#pragma unroll
            for (int ni = 0; ni < 8; ni++)
#pragma unroll
                for (int j = 0; j < 4; j++) acc[mi][ni][j] = 0.f;

#pragma unroll 4
        for (int k0 = 0; k0 < 16; k0++) {
            const int k = k0 * 8;
            uint32_t a[2][4], b[8][2];
#pragma unroll
            for (int mi = 0; mi < 2; mi++) {
                int r = mb + mi * 16 + g;
                a[mi][0] = xs[r * PSTR + k + tq];
                a[mi][1] = xs[(r + 8) * PSTR + k + tq];
                a[mi][2] = xs[r * PSTR + k + tq + 4];
                a[mi][3] = xs[(r + 8) * PSTR + k + tq + 4];
            }
#pragma unroll
            for (int ni = 0; ni < 8; ni++) {
                int col = nb + ni * 8 + g;
                b[ni][0] = ws[(k + tq) * PSTR + col];
                b[ni][1] = ws[(k + tq + 4) * PSTR + col];
            }
#pragma unroll
            for (int mi = 0; mi < 2; mi++)
#pragma unroll
                for (int ni = 0; ni < 8; ni++)
                    mma_tf32(acc[mi][ni], a[mi], b[ni]);
        }

        __syncthreads();
        float* stg = (float*)ws;
#pragma unroll
        for (int mi = 0; mi < 2; mi++) {
#pragma unroll
            for (int ni = 0; ni < 8; ni++) {
                int r = mb + mi * 16 + g;
                int c = nb + ni * 8 + 2 * tq;
                float2 lo = {acc[mi][ni][0], acc[mi][ni][1]};
                float2 hi = {acc[mi][ni][2], acc[mi][ni][3]};
                *(float2*)&stg[r * PSTR + c] = lo;
                *(float2*)&stg[(r + 8) * PSTR + c] = hi;
            }
        }
        __syncthreads();

        if (m == 1) {
            // q: fold SCALE, convert to tf32 bits
            uint32_t* dq = (uint32_t*)dlist[1];
            for (int i = t; i < 128 * 32; i += 256) {
                int r = i >> 5, c = (i & 31) * 4;
                float4 v = *(float4*)&stg[r * PSTR + c];
                uint4 w = {f2tf32(v.x * SCALE), f2tf32(v.y * SCALE),
                           f2tf32(v.z * SCALE), f2tf32(v.w * SCALE)};
                *(uint4*)&dq[(size_t)r * HH + c] = w;
            }
        } else {
            float* dst = dlist[m];
            for (int i = t; i < 128 * 32; i += 256) {
                int r = i >> 5, c = (i & 31) * 4;
                *(float4*)&dst[(size_t)r * HH + c] = *(float4*)&stg[r * PSTR + c];
            }
        }
    }
}

// ---------------------------------------------------------------------------
// Kernel 2: causal flash attention, GEMMs on tensor pipe (mma.sync tf32).
// Grid: (4 q-blocks, 512 batches) x 256 threads (8 warps).
// S^T = K @ Q^T (fragments stored transposed -> S[query][key]);
// softmax row-wise; P stored as tf32 bits in place; O = P @ V in fragments.
// ---------------------------------------------------------------------------
#define AQ 136   // q/k/v smem stride (words); 136%32==8 -> conflict-free frags
#define ASS 68   // S stride; 68%32==4
#define ATTN_SMEM ((3 * 64 * AQ + 64 * ASS + 3 * 64) * 4)

__global__ void __launch_bounds__(256) attn_kernel(float* __restrict__ dout)
{
    extern __shared__ uint32_t usm[];
    uint32_t* qs = usm;               // 64 x 136 tf32 bits (pre-scaled)
    uint32_t* ks = qs + 64 * AQ;      // 64 x 136 tf32 bits
    uint32_t* vs = ks + 64 * AQ;      // 64 x 136 tf32 bits
    float* S   = (float*)(vs + 64 * AQ);  // 64 x 68 (scores fp32 / P tf32 bits)
    float* m_s = S + 64 * ASS;
    float* l_s = m_s + 64;
    float* f_s = l_s + 64;

    const int t    = threadIdx.x;
    const int warp = t >> 5;
    const int lane = t & 31;
    const int g  = lane >> 2;
    const int tq = lane & 3;
    const int qb = blockIdx.x;
    const int b  = blockIdx.y;
    const int qr0 = qb * 64;

    const uint32_t* qg = (const uint32_t*)g_q + ((size_t)b * TT + qr0) * HH;
    const float* kg = dout + BTH + (size_t)b * TT * HH;
    const float* vg = dout + 2 * BTH + (size_t)b * TT * HH;

    // load q tile (already tf32 bits)
    for (int i = t; i < 64 * 32; i += 256) {
        int r = i >> 5, c4 = i & 31;
        *(uint4*)&qs[r * AQ + c4 * 4] = ((const uint4*)qg)[i];
    }
    if (t < 64) { m_s[t] = -1e30f; l_s[t] = 0.f; }

    // S^T warp tiling: keys m = (warp&3)*16, queries n = (warp>>2)*32
    const int mK = (warp & 3) * 16;
    const int nQ = (warp >> 2) * 32;
    // PV warp tiling: queries m = (warp&1)*32, head n = (warp>>1)*32
    const int mQ = (warp & 1) * 32;
    const int nH = (warp >> 1) * 32;

    float oacc[2][4][4];
#pragma unroll
    for (int mt = 0; mt < 2; mt++)
#pragma unroll
        for (int ni = 0; ni < 4; ni++)
#pragma unroll
            for (int j = 0; j < 4; j++) oacc[mt][ni][j] = 0.f;

    for (int kt = 0; kt <= qb; kt++) {
        __syncthreads();
        // load K/V tiles, convert to tf32 (coalesced LDG.128, STS.128)
        {
            const float4* kgt = (const float4*)(kg + (size_t)kt * 64 * HH);
            const float4* vgt = (const float4*)(vg + (size_t)kt * 64 * HH);
            for (int i = t; i < 64 * 32; i += 256) {
                int r = i >> 5, c4 = i & 31;
                float4 kv = kgt[i];
                uint4 kw = {f2tf32(kv.x), f2tf32(kv.y), f2tf32(kv.z), f2tf32(kv.w)};
                *(uint4*)&ks[r * AQ + c4 * 4] = kw;
                float4 vv = vgt[i];
                uint4 vw = {f2tf32(vv.x), f2tf32(vv.y), f2tf32(vv.z), f2tf32(vv.w)};
                *(uint4*)&vs[r * AQ + c4 * 4] = vw;
            }
        }
        __syncthreads();

        // ---- Phase A: S^T = K @ Q^T  (M=64 keys, N=64 queries, K=128)
        {
            float sacc[4][4];
#pragma unroll
            for (int ni = 0; ni < 4; ni++)
#pragma unroll
                for (int j = 0; j < 4; j++) sacc[ni][j] = 0.f;

#pragma unroll 4
            for (int k0 = 0; k0 < 16; k0++) {
                const int k = k0 * 8;
                uint32_t a[4];
                a[0] = ks[(mK + g) * AQ + k + tq];
                a[1] = ks[(mK + g + 8) * AQ + k + tq];
                a[2] = ks[(mK + g) * AQ + k + tq + 4];
                a[3] = ks[(mK + g + 8) * AQ + k + tq + 4];
#pragma unroll
                for (int ni = 0; ni < 4; ni++) {
                    int col = nQ + ni * 8 + g;
                    uint32_t bf[2] = {qs[col * AQ + k + tq], qs[col * AQ + k + tq + 4]};
                    mma_tf32(sacc[ni], a, bf);
                }
            }

            // store fragments transposed -> S[query][key], causal mask on diag
            const bool diag = (kt == qb);
#pragma unroll
            for (int ni = 0; ni < 4; ni++) {
                int colq = nQ + ni * 8 + 2 * tq;
#pragma unroll
                for (int j = 0; j < 4; j++) {
                    int key = mK + g + ((j >> 1) * 8);
                    int qi  = colq + (j & 1);
                    float sv = sacc[ni][j];
                    if (diag && key > qi) sv = -1e30f;
                    S[qi * ASS + key] = sv;
                }
            }
        }
        __syncthreads();

        // ---- Phase B: online softmax (4 threads/row); P stored as tf32 bits
        {
            const int rB = t >> 2;
            const int cbB = (t & 3) * 16;
            float tm = -1e30f;
#pragma unroll
            for (int i = 0; i < 16; i++)
                tm = fmaxf(tm, S[rB * ASS + cbB + i]);
            tm = fmaxf(tm, __shfl_xor_sync(0xFFFFFFFFu, tm, 1));
            tm = fmaxf(tm, __shfl_xor_sync(0xFFFFFFFFu, tm, 2));

            float mo = m_s[rB];
            float nm = fmaxf(mo, tm);
            float ps = 0.f;
#pragma unroll
            for (int i = 0; i < 16; i++) {
                float p = __expf(S[rB * ASS + cbB + i] - nm);
                S[rB * ASS + cbB + i] = __uint_as_float(f2tf32(p));
                ps += p;
            }
            ps += __shfl_xor_sync(0xFFFFFFFFu, ps, 1);
            ps += __shfl_xor_sync(0xFFFFFFFFu, ps, 2);

            if ((t & 3) == 0) {
                float f = __expf(mo - nm);
                l_s[rB] = l_s[rB] * f + ps;
                m_s[rB] = nm;
                f_s[rB] = f;
            }
        }
        __syncthreads();

        // ---- Phase C: O = O*f + P @ V  (M=64 queries, N=128 head, K=64 keys)
        {
#pragma unroll
            for (int mt = 0; mt < 2; mt++) {
                float f0 = f_s[mQ + mt * 16 + g];
                float f8 = f_s[mQ + mt * 16 + g + 8];
#pragma unroll
                for (int ni = 0; ni < 4; ni++) {
                    oacc[mt][ni][0] *= f0; oacc[mt][ni][1] *= f0;
                    oacc[mt][ni][2] *= f8; oacc[mt][ni][3] *= f8;
                }
            }
#pragma unroll 4
            for (int k0 = 0; k0 < 8; k0++) {
                const int k = k0 * 8;
                uint32_t a[2][4], bf[4][2];
#pragma unroll
                for (int mt = 0; mt < 2; mt++) {
                    int r0 = mQ + mt * 16 + g;
                    a[mt][0] = __float_as_uint(S[r0 * ASS + k + tq]);
                    a[mt][1] = __float_as_uint(S[(r0 + 8) * ASS + k + tq]);
                    a[mt][2] = __float_as_uint(S[r0 * ASS + k + tq + 4]);
                    a[mt][3] = __float_as_uint(S[(r0 + 8) * ASS + k + tq + 4]);
                }
#pragma unroll
                for (int ni = 0; ni < 4; ni++) {
                    int ch = nH + ni * 8 + g;
                    bf[ni][0] = vs[(k + tq) * AQ + ch];
                    bf[ni][1] = vs[(k + tq + 4) * AQ + ch];
                }
#pragma unroll
                for (int mt = 0; mt < 2; mt++)
#pragma unroll
                    for (int ni = 0; ni < 4; ni++)
                        mma_tf32(oacc[mt][ni], a[mt], bf[ni]);
            }
        }
    }

    // ---- epilogue: normalize by 1/l, store
#pragma unroll
    for (int mt = 0; mt < 2; mt++) {
        int r0 = mQ + mt * 16 + g;
        float i0 = 1.f / l_s[r0];
        float i8 = 1.f / l_s[r0 + 8];
#pragma unroll
        for (int ni = 0; ni < 4; ni++) {
            int c = nH + ni * 8 + 2 * tq;
            float2 lo = {oacc[mt][ni][0] * i0, oacc[mt][ni][1] * i0};
            float2 hi = {oacc[mt][ni][2] * i8, oacc[mt][ni][3] * i8};
            *(float2*)&dout[((size_t)b * TT + qr0 + r0) * HH + c] = lo;
            *(float2*)&dout[((size_t)b * TT + qr0 + r0 + 8) * HH + c] = hi;
        }
    }
}

// ---------------------------------------------------------------------------
extern "C" void kernel_launch(void* const* d_in, const int* in_sizes, int n_in,
                              void* d_out, int out_size)
{
    const float* x  = (const float*)d_in[0];
    const float* Wk = (const float*)d_in[1];
    const float* Wq = (const float*)d_in[2];
    const float* Wv = (const float*)d_in[3];
    float* out = (float*)d_out;

    cudaFuncSetAttribute(proj_kernel, cudaFuncAttributeMaxDynamicSharedMemorySize, PROJ_SMEM);
    cudaFuncSetAttribute(attn_kernel, cudaFuncAttributeMaxDynamicSharedMemorySize, ATTN_SMEM);

    proj_kernel<<<(BB * TT) / 128, 256, PROJ_SMEM>>>(x, Wk, Wq, Wv, out);
    attn_kernel<<<dim3(4, BB), 256, ATTN_SMEM>>>(out);
}

// round 13
// speedup vs baseline: 3.0688x; 1.3844x over previous
#include <cuda_runtime.h>
#include <cstdint>

#define BB 512
#define TT 256
#define CC 128
#define HH 128
#define BTH ((size_t)BB * TT * HH)

// scratch for q projection: holds tf32 BITS of q*scale (written by proj)
static __device__ float g_q[BTH];

// ============================ helpers ======================================
__device__ __forceinline__ uint32_t f2tf32(float f) {
    uint32_t r;
    asm("cvt.rna.tf32.f32 %0, %1;" : "=r"(r) : "f"(f));
    return r;
}

// m16n8k8 tf32 mma, fp32 accumulate (portable mma.sync — works on compute_103)
__device__ __forceinline__ void mma_tf32(float* c, const uint32_t* a, const uint32_t* b) {
    asm volatile(
        "mma.sync.aligned.m16n8k8.row.col.f32.tf32.tf32.f32 "
        "{%0,%1,%2,%3}, {%4,%5,%6,%7}, {%8,%9}, {%0,%1,%2,%3};"
        : "+f"(c[0]), "+f"(c[1]), "+f"(c[2]), "+f"(c[3])
        : "r"(a[0]), "r"(a[1]), "r"(a[2]), "r"(a[3]), "r"(b[0]), "r"(b[1]));
}

#define SCALE 0.08838834764831845f  // 128^-0.5 (n_embd scaling)

// ---------------------------------------------------------------------------
// Kernel 1: fused QKV projection via mma.sync tf32, 64-row tiles for 2 CTA/SM.
// Grid: B*T/64 = 2048 CTAs x 256 threads (8 warps).
// Per CTA: out[64x128] = x[64x128] @ W[128x128], for Wk, Wq, Wv.
// Warp w: rows mb=(w&1)*32, cols nb=(w>>1)*32. 2 m-frags x 4 n-frags.
// smem: xs 64x136 + ws 128x136 = 104,448 B -> 2 CTAs/SM.
// ---------------------------------------------------------------------------
#define PSTR 136
#define PROJ_SMEM ((64 * PSTR + 128 * PSTR) * 4)

__global__ void __launch_bounds__(256, 2) proj_kernel(
    const float* __restrict__ x,
    const float* __restrict__ Wk,
    const float* __restrict__ Wq,
    const float* __restrict__ Wv,
    float* __restrict__ out)
{
    extern __shared__ uint32_t usm[];
    uint32_t* xs = usm;              // 64 x 136 (tf32 bits)
    uint32_t* ws = usm + 64 * PSTR;  // 128 x 136 (tf32 bits / fp32 staging)

    const int t    = threadIdx.x;
    const int warp = t >> 5;
    const int lane = t & 31;
    const int g  = lane >> 2;
    const int tq = lane & 3;
    const size_t row0 = (size_t)blockIdx.x * 64;

    // load x tile [64 x 128] -> xs (tf32)
    {
        const float4* xg = (const float4*)(x + row0 * CC);
        for (int i = t; i < 64 * 32; i += 256) {
            int r = i >> 5, c = (i & 31) * 4;
            float4 v = xg[i];
            uint32_t* d = &xs[r * PSTR + c];
            d[0] = f2tf32(v.x); d[1] = f2tf32(v.y);
            d[2] = f2tf32(v.z); d[3] = f2tf32(v.w);
        }
    }

    const float* Wlist[3] = {Wk, Wq, Wv};
    float* dlist[3] = {out + BTH + row0 * HH,       // k
                       g_q + row0 * HH,             // q (tf32 bits, scaled)
                       out + 2 * BTH + row0 * HH};  // v

    const int mb = (warp & 1) * 32;
    const int nb = (warp >> 1) * 32;

    for (int m = 0; m < 3; m++) {
        __syncthreads();   // prior epilogue readers of ws done
        // load W [k=128][n=128] -> ws (tf32)
        {
            const float4* Wg = (const float4*)Wlist[m];
            for (int i = t; i < 128 * 32; i += 256) {
                int kr = i >> 5, n = (i & 31) * 4;
                float4 v = Wg[i];
                uint32_t* d = &ws[kr * PSTR + n];
                d[0] = f2tf32(v.x); d[1] = f2tf32(v.y);
                d[2] = f2tf32(v.z); d[3] = f2tf32(v.w);
            }
        }
        __syncthreads();

        float acc[2][4][4];
#pragma unroll
        for (int mi = 0; mi < 2; mi++)
#pragma unroll
            for (int ni = 0; ni < 4; ni++)
#pragma unroll
                for (int j = 0; j < 4; j++) acc[mi][ni][j] = 0.f;

#pragma unroll 4
        for (int k0 = 0; k0 < 16; k0++) {
            const int k = k0 * 8;
            uint32_t a[2][4], b[4][2];
#pragma unroll
            for (int mi = 0; mi < 2; mi++) {
                int r = mb + mi * 16 + g;
                a[mi][0] = xs[r * PSTR + k + tq];
                a[mi][1] = xs[(r + 8) * PSTR + k + tq];
                a[mi][2] = xs[r * PSTR + k + tq + 4];
                a[mi][3] = xs[(r + 8) * PSTR + k + tq + 4];
            }
#pragma unroll
            for (int ni = 0; ni < 4; ni++) {
                int col = nb + ni * 8 + g;
                b[ni][0] = ws[(k + tq) * PSTR + col];
                b[ni][1] = ws[(k + tq + 4) * PSTR + col];
            }
#pragma unroll
            for (int mi = 0; mi < 2; mi++)
#pragma unroll
                for (int ni = 0; ni < 4; ni++)
                    mma_tf32(acc[mi][ni], a[mi], b[ni]);
        }

        __syncthreads();   // mma reads of ws done -> reuse as staging
        float* stg = (float*)ws;
#pragma unroll
        for (int mi = 0; mi < 2; mi++) {
#pragma unroll
            for (int ni = 0; ni < 4; ni++) {
                int r = mb + mi * 16 + g;
                int c = nb + ni * 8 + 2 * tq;
                float2 lo = {acc[mi][ni][0], acc[mi][ni][1]};
                float2 hi = {acc[mi][ni][2], acc[mi][ni][3]};
                *(float2*)&stg[r * PSTR + c] = lo;
                *(float2*)&stg[(r + 8) * PSTR + c] = hi;
            }
        }
        __syncthreads();

        if (m == 1) {
            // q: fold SCALE, convert to tf32 bits
            uint32_t* dq = (uint32_t*)dlist[1];
            for (int i = t; i < 64 * 32; i += 256) {
                int r = i >> 5, c = (i & 31) * 4;
                float4 v = *(float4*)&stg[r * PSTR + c];
                uint4 w = {f2tf32(v.x * SCALE), f2tf32(v.y * SCALE),
                           f2tf32(v.z * SCALE), f2tf32(v.w * SCALE)};
                *(uint4*)&dq[(size_t)r * HH + c] = w;
            }
        } else {
            float* dst = dlist[m];
            for (int i = t; i < 64 * 32; i += 256) {
                int r = i >> 5, c = (i & 31) * 4;
                *(float4*)&dst[(size_t)r * HH + c] = *(float4*)&stg[r * PSTR + c];
            }
        }
    }
}

// ---------------------------------------------------------------------------
// Kernel 2: causal flash attention, tensor-pipe GEMMs, K/V overlaid in one
// smem buffer -> 87.8 KB -> 2 CTAs/SM. V global load overlapped with softmax.
// Grid: (4 q-blocks, 512 batches) x 256 threads (8 warps).
// ---------------------------------------------------------------------------
#define AQ 136   // q/kv smem stride (words); 136%32==8 -> conflict-free frags
#define ASS 68   // S stride; 68%32==4
#define ATTN_SMEM ((2 * 64 * AQ + 64 * ASS + 3 * 64) * 4)

__global__ void __launch_bounds__(256, 2) attn_kernel(float* __restrict__ dout)
{
    extern __shared__ uint32_t usm[];
    uint32_t* qs  = usm;               // 64 x 136 tf32 bits (pre-scaled)
    uint32_t* kvs = qs + 64 * AQ;      // 64 x 136 tf32 bits (K, then V)
    float* S   = (float*)(kvs + 64 * AQ);  // 64 x 68 (scores / P tf32 bits)
    float* m_s = S + 64 * ASS;
    float* l_s = m_s + 64;
    float* f_s = l_s + 64;

    const int t    = threadIdx.x;
    const int warp = t >> 5;
    const int lane = t & 31;
    const int g  = lane >> 2;
    const int tq = lane & 3;
    const int qb = blockIdx.x;
    const int b  = blockIdx.y;
    const int qr0 = qb * 64;

    const uint32_t* qg = (const uint32_t*)g_q + ((size_t)b * TT + qr0) * HH;
    const float* kg = dout + BTH + (size_t)b * TT * HH;
    const float* vg = dout + 2 * BTH + (size_t)b * TT * HH;

    // load q tile (already tf32 bits)
    for (int i = t; i < 64 * 32; i += 256) {
        int r = i >> 5, c4 = i & 31;
        *(uint4*)&qs[r * AQ + c4 * 4] = ((const uint4*)qg)[i];
    }
    if (t < 64) { m_s[t] = -1e30f; l_s[t] = 0.f; }

    // S^T warp tiling: keys m = (warp&3)*16, queries n = (warp>>2)*32
    const int mK = (warp & 3) * 16;
    const int nQ = (warp >> 2) * 32;
    // PV warp tiling: queries m = (warp&1)*32, head n = (warp>>1)*32
    const int mQ = (warp & 1) * 32;
    const int nH = (warp >> 1) * 32;

    float oacc[2][4][4];
#pragma unroll
    for (int mt = 0; mt < 2; mt++)
#pragma unroll
        for (int ni = 0; ni < 4; ni++)
#pragma unroll
            for (int j = 0; j < 4; j++) oacc[mt][ni][j] = 0.f;

    for (int kt = 0; kt <= qb; kt++) {
        __syncthreads();   // prior Phase C reads of kvs (V) done
        // load K tile -> kvs
        {
            const float4* kgt = (const float4*)(kg + (size_t)kt * 64 * HH);
            for (int i = t; i < 64 * 32; i += 256) {
                int r = i >> 5, c4 = i & 31;
                float4 kv = kgt[i];
                uint4 kw = {f2tf32(kv.x), f2tf32(kv.y), f2tf32(kv.z), f2tf32(kv.w)};
                *(uint4*)&kvs[r * AQ + c4 * 4] = kw;
            }
        }
        __syncthreads();

        // ---- Phase A: S^T = K @ Q^T  (M=64 keys, N=64 queries, K=128)
        {
            float sacc[4][4];
#pragma unroll
            for (int ni = 0; ni < 4; ni++)
#pragma unroll
                for (int j = 0; j < 4; j++) sacc[ni][j] = 0.f;

#pragma unroll 4
            for (int k0 = 0; k0 < 16; k0++) {
                const int k = k0 * 8;
                uint32_t a[4];
                a[0] = kvs[(mK + g) * AQ + k + tq];
                a[1] = kvs[(mK + g + 8) * AQ + k + tq];
                a[2] = kvs[(mK + g) * AQ + k + tq + 4];
                a[3] = kvs[(mK + g + 8) * AQ + k + tq + 4];
#pragma unroll
                for (int ni = 0; ni < 4; ni++) {
                    int col = nQ + ni * 8 + g;
                    uint32_t bf[2] = {qs[col * AQ + k + tq], qs[col * AQ + k + tq + 4]};
                    mma_tf32(sacc[ni], a, bf);
                }
            }

            // store fragments transposed -> S[query][key], causal mask on diag
            const bool diag = (kt == qb);
#pragma unroll
            for (int ni = 0; ni < 4; ni++) {
                int colq = nQ + ni * 8 + 2 * tq;
#pragma unroll
                for (int j = 0; j < 4; j++) {
                    int key = mK + g + ((j >> 1) * 8);
                    int qi  = colq + (j & 1);
                    float sv = sacc[ni][j];
                    if (diag && key > qi) sv = -1e30f;
                    S[qi * ASS + key] = sv;
                }
            }
        }
        __syncthreads();   // A's reads of kvs(K) + writes of S done

        // ---- V global load (into regs, hidden behind softmax) ----
        float4 vreg[8];
        {
            const float4* vgt = (const float4*)(vg + (size_t)kt * 64 * HH);
#pragma unroll
            for (int j = 0; j < 8; j++)
                vreg[j] = vgt[t + 256 * j];
        }

        // ---- Phase B: online softmax (4 threads/row); P stored as tf32 bits
        {
            const int rB = t >> 2;
            const int cbB = (t & 3) * 16;
            float tm = -1e30f;
#pragma unroll
            for (int i = 0; i < 16; i++)
                tm = fmaxf(tm, S[rB * ASS + cbB + i]);
            tm = fmaxf(tm, __shfl_xor_sync(0xFFFFFFFFu, tm, 1));
            tm = fmaxf(tm, __shfl_xor_sync(0xFFFFFFFFu, tm, 2));

            float mo = m_s[rB];
            float nm = fmaxf(mo, tm);
            float ps = 0.f;
#pragma unroll
            for (int i = 0; i < 16; i++) {
                float p = __expf(S[rB * ASS + cbB + i] - nm);
                S[rB * ASS + cbB + i] = __uint_as_float(f2tf32(p));
                ps += p;
            }
            ps += __shfl_xor_sync(0xFFFFFFFFu, ps, 1);
            ps += __shfl_xor_sync(0xFFFFFFFFu, ps, 2);

            if ((t & 3) == 0) {
                float f = __expf(mo - nm);
                l_s[rB] = l_s[rB] * f + ps;
                m_s[rB] = nm;
                f_s[rB] = f;
            }
        }

        // ---- store V into kvs (K no longer needed) ----
#pragma unroll
        for (int j = 0; j < 8; j++) {
            int i = t + 256 * j;
            int r = i >> 5, c4 = i & 31;
            uint4 vw = {f2tf32(vreg[j].x), f2tf32(vreg[j].y),
                        f2tf32(vreg[j].z), f2tf32(vreg[j].w)};
            *(uint4*)&kvs[r * AQ + c4 * 4] = vw;
        }
        __syncthreads();   // V staged + softmax done

        // ---- Phase C: O = O*f + P @ V  (M=64 queries, N=128 head, K=64 keys)
        {
#pragma unroll
            for (int mt = 0; mt < 2; mt++) {
                float f0 = f_s[mQ + mt * 16 + g];
                float f8 = f_s[mQ + mt * 16 + g + 8];
#pragma unroll
                for (int ni = 0; ni < 4; ni++) {
                    oacc[mt][ni][0] *= f0; oacc[mt][ni][1] *= f0;
                    oacc[mt][ni][2] *= f8; oacc[mt][ni][3] *= f8;
                }
            }
#pragma unroll 4
            for (int k0 = 0; k0 < 8; k0++) {
                const int k = k0 * 8;
                uint32_t a[2][4], bf[4][2];
#pragma unroll
                for (int mt = 0; mt < 2; mt++) {
                    int r0 = mQ + mt * 16 + g;
                    a[mt][0] = __float_as_uint(S[r0 * ASS + k + tq]);
                    a[mt][1] = __float_as_uint(S[(r0 + 8) * ASS + k + tq]);
                    a[mt][2] = __float_as_uint(S[r0 * ASS + k + tq + 4]);
                    a[mt][3] = __float_as_uint(S[(r0 + 8) * ASS + k + tq + 4]);
                }
#pragma unroll
                for (int ni = 0; ni < 4; ni++) {
                    int ch = nH + ni * 8 + g;
                    bf[ni][0] = kvs[(k + tq) * AQ + ch];
                    bf[ni][1] = kvs[(k + tq + 4) * AQ + ch];
                }
#pragma unroll
                for (int mt = 0; mt < 2; mt++)
#pragma unroll
                    for (int ni = 0; ni < 4; ni++)
                        mma_tf32(oacc[mt][ni], a[mt], bf[ni]);
            }
        }
    }

    // ---- epilogue: normalize by 1/l, store
#pragma unroll
    for (int mt = 0; mt < 2; mt++) {
        int r0 = mQ + mt * 16 + g;
        float i0 = 1.f / l_s[r0];
        float i8 = 1.f / l_s[r0 + 8];
#pragma unroll
        for (int ni = 0; ni < 4; ni++) {
            int c = nH + ni * 8 + 2 * tq;
            float2 lo = {oacc[mt][ni][0] * i0, oacc[mt][ni][1] * i0};
            float2 hi = {oacc[mt][ni][2] * i8, oacc[mt][ni][3] * i8};
            *(float2*)&dout[((size_t)b * TT + qr0 + r0) * HH + c] = lo;
            *(float2*)&dout[((size_t)b * TT + qr0 + r0 + 8) * HH + c] = hi;
        }
    }
}

// ---------------------------------------------------------------------------
extern "C" void kernel_launch(void* const* d_in, const int* in_sizes, int n_in,
                              void* d_out, int out_size)
{
    const float* x  = (const float*)d_in[0];
    const float* Wk = (const float*)d_in[1];
    const float* Wq = (const float*)d_in[2];
    const float* Wv = (const float*)d_in[3];
    float* out = (float*)d_out;

    cudaFuncSetAttribute(proj_kernel, cudaFuncAttributeMaxDynamicSharedMemorySize, PROJ_SMEM);
    cudaFuncSetAttribute(attn_kernel, cudaFuncAttributeMaxDynamicSharedMemorySize, ATTN_SMEM);

    proj_kernel<<<(BB * TT) / 64, 256, PROJ_SMEM>>>(x, Wk, Wq, Wv, out);
    attn_kernel<<<dim3(4, BB), 256, ATTN_SMEM>>>(out);
}